// round 16
// baseline (speedup 1.0000x reference)
#include <cuda_runtime.h>
#include <cuda_bf16.h>
#include <math.h>
#include <stdint.h>

// ---------------------------------------------------------------------------
// GRU LM: T=128, B=64, E=H=512, V=10000, 2 layers.
// Round 16: r15 (4044us) with ONE change in k_recur_mma: staging becomes
// 4 chunks x 32KB, ALL issued upfront, incremental wait_group 3/2/1/0 ->
// 4 waits + 4 syncs per phase (was 8 waits + 16 syncs), max overlap.
// ---------------------------------------------------------------------------

#define TT   128
#define BB   64
#define HH   512
#define VV   10000
#define MALL (TT * BB)   // 8192
#define GK   512

#define RBLK 64          // recurrence blocks
#define NTHR 256

// fp32 scratch
__device__ float g_emb [MALL * HH];
__device__ float g_gx  [MALL * 3 * HH];
__device__ float g_inp [MALL * HH];
__device__ float g_hcur[BB * HH];
__device__ float g_z   [BB * HH];
__device__ float g_wxT [2 * 3 * HH * HH];
__device__ float g_uT  [2 * HH * HH];      // transpose staging

// bf16 hi/lo planes
__device__ __nv_bfloat16 g_ahi  [MALL * GK];
__device__ __nv_bfloat16 g_alo  [MALL * GK];
__device__ __nv_bfloat16 g_hallh[MALL * GK];
__device__ __nv_bfloat16 g_halll[MALL * GK];
__device__ __nv_bfloat16 g_hch  [BB * HH];
__device__ __nv_bfloat16 g_hcl  [BB * HH];
__device__ __nv_bfloat16 g_rhh  [BB * HH];
__device__ __nv_bfloat16 g_rhl  [BB * HH];
__device__ __nv_bfloat16 g_wxh [2 * 3 * HH * HH];
__device__ __nv_bfloat16 g_wxl [2 * 3 * HH * HH];
__device__ __nv_bfloat16 g_fch [2 * HH * HH];
__device__ __nv_bfloat16 g_fcl [2 * HH * HH];
__device__ __nv_bfloat16 g_dech[VV * HH];
__device__ __nv_bfloat16 g_decl[VV * HH];
__device__ __nv_bfloat16 g_uhTh [2 * 2 * HH * HH];
__device__ __nv_bfloat16 g_uhTl [2 * 2 * HH * HH];
__device__ __nv_bfloat16 g_uhtTh[2 * HH * HH];
__device__ __nv_bfloat16 g_uhtTl[2 * HH * HH];

// grid barrier state (r7, self-resetting)
__device__ unsigned g_bar_cnt = 0;
__device__ unsigned g_bar_gen = 0;

// ---------------------------------------------------------------------------
__global__ void k_gather(const int* __restrict__ inp, const float* __restrict__ tbl) {
    int i   = blockIdx.x;
    int row = inp[i];
    const float4* src = reinterpret_cast<const float4*>(tbl + (size_t)row * HH);
    float4*       dst = reinterpret_cast<float4*>(g_emb + (size_t)i * HH);
    for (int j = threadIdx.x; j < HH / 4; j += blockDim.x) dst[j] = src[j];
}

__global__ void k_transpose(const float* __restrict__ W, float* __restrict__ WT,
                            int K, int N) {
    __shared__ float tile[32][33];
    int k0 = blockIdx.y * 32, n0 = blockIdx.x * 32;
    int tx = threadIdx.x, ty = threadIdx.y;
#pragma unroll
    for (int i = 0; i < 32; i += 8)
        if (k0 + ty + i < K && n0 + tx < N)
            tile[ty + i][tx] = W[(size_t)(k0 + ty + i) * N + n0 + tx];
    __syncthreads();
#pragma unroll
    for (int i = 0; i < 32; i += 8)
        if (n0 + ty + i < N && k0 + tx < K)
            WT[(size_t)(n0 + ty + i) * K + k0 + tx] = tile[tx][ty + i];
}

__global__ void k_cvt(const float* __restrict__ src,
                      __nv_bfloat16* __restrict__ hi,
                      __nv_bfloat16* __restrict__ lo, int n4) {
    int i = blockIdx.x * blockDim.x + threadIdx.x;
    if (i >= n4) return;
    float4 v = reinterpret_cast<const float4*>(src)[i];
    __nv_bfloat16 h0 = __float2bfloat16(v.x), h1 = __float2bfloat16(v.y),
                  h2 = __float2bfloat16(v.z), h3 = __float2bfloat16(v.w);
    __nv_bfloat16 l0 = __float2bfloat16(v.x - __bfloat162float(h0));
    __nv_bfloat16 l1 = __float2bfloat16(v.y - __bfloat162float(h1));
    __nv_bfloat16 l2 = __float2bfloat16(v.z - __bfloat162float(h2));
    __nv_bfloat16 l3 = __float2bfloat16(v.w - __bfloat162float(h3));
    uint2 hv, lv;
    hv.x = (uint32_t)__bfloat16_as_ushort(h0) | ((uint32_t)__bfloat16_as_ushort(h1) << 16);
    hv.y = (uint32_t)__bfloat16_as_ushort(h2) | ((uint32_t)__bfloat16_as_ushort(h3) << 16);
    lv.x = (uint32_t)__bfloat16_as_ushort(l0) | ((uint32_t)__bfloat16_as_ushort(l1) << 16);
    lv.y = (uint32_t)__bfloat16_as_ushort(l2) | ((uint32_t)__bfloat16_as_ushort(l3) << 16);
    reinterpret_cast<uint2*>(hi)[i] = hv;
    reinterpret_cast<uint2*>(lo)[i] = lv;
}

// ---------------------------------------------------------------------------
// mma.sync helpers
// ---------------------------------------------------------------------------
__device__ __forceinline__ void cpasync16(void* dst_smem, const void* src) {
    uint32_t d = (uint32_t)__cvta_generic_to_shared(dst_smem);
    asm volatile("cp.async.cg.shared.global [%0], [%1], 16;" :: "r"(d), "l"(src));
}
__device__ __forceinline__ void cpasync16z(void* dst_smem, const void* src, int sz) {
    uint32_t d = (uint32_t)__cvta_generic_to_shared(dst_smem);
    asm volatile("cp.async.cg.shared.global [%0], [%1], 16, %2;"
                 :: "r"(d), "l"(src), "r"(sz));
}
__device__ __forceinline__ void cp_commit() { asm volatile("cp.async.commit_group;"); }

__device__ __forceinline__ void ldmx4(uint32_t* r, uint32_t addr) {
    asm volatile("ldmatrix.sync.aligned.m8n8.x4.shared.b16 {%0,%1,%2,%3}, [%4];"
                 : "=r"(r[0]), "=r"(r[1]), "=r"(r[2]), "=r"(r[3]) : "r"(addr));
}
__device__ __forceinline__ void mma16816(float* d, const uint32_t* a, const uint32_t* b) {
    asm volatile(
        "mma.sync.aligned.m16n8k16.row.col.f32.bf16.bf16.f32 "
        "{%0,%1,%2,%3}, {%4,%5,%6,%7}, {%8,%9}, {%0,%1,%2,%3};"
        : "+f"(d[0]), "+f"(d[1]), "+f"(d[2]), "+f"(d[3])
        : "r"(a[0]), "r"(a[1]), "r"(a[2]), "r"(a[3]), "r"(b[0]), "r"(b[1]));
}

__device__ __forceinline__ uint32_t pack_hl_hi(float x, float y) {
    __nv_bfloat16 hx = __float2bfloat16(x), hy = __float2bfloat16(y);
    return (uint32_t)__bfloat16_as_ushort(hx) | ((uint32_t)__bfloat16_as_ushort(hy) << 16);
}
__device__ __forceinline__ uint32_t pack_hl_lo(float x, float y) {
    __nv_bfloat16 hx = __float2bfloat16(x), hy = __float2bfloat16(y);
    __nv_bfloat16 lx = __float2bfloat16(x - __bfloat162float(hx));
    __nv_bfloat16 ly = __float2bfloat16(y - __bfloat162float(hy));
    return (uint32_t)__bfloat16_as_ushort(lx) | ((uint32_t)__bfloat16_as_ushort(ly) << 16);
}

// ---------------------------------------------------------------------------
// Tensor-core GEMM (r12, measured): interleaved 3-product bf16x3.
// ---------------------------------------------------------------------------
#define NCH 16

__global__ __launch_bounds__(256)
void k_gemm_tc(const __nv_bfloat16* __restrict__ Ahi,
               const __nv_bfloat16* __restrict__ Alo,
               const __nv_bfloat16* __restrict__ Bhi,
               const __nv_bfloat16* __restrict__ Blo,
               const float* __restrict__ bias, float* __restrict__ C, int N) {
    extern __shared__ __align__(16) char smem[];

    const int tid  = threadIdx.x;
    const int lane = tid & 31;
    const int wid  = tid >> 5;
    const int wm   = wid >> 2;
    const int wn   = wid & 3;
    const int m0   = blockIdx.y * 128;
    const int n0   = blockIdx.x * 128;

    const int sRow0 = tid >> 2;
    const int sC16  = tid & 3;
    const int sSw0  = sC16 ^ ((sRow0 >> 1) & 3);
    const int sRow1 = sRow0 + 64;
    const int sSw1  = sC16 ^ ((sRow1 >> 1) & 3);

    const int aRow16 = lane & 15;
    const int aKhalf = lane >> 4;
    const int bL8 = lane & 7, bG = lane >> 3;

    int  aRowOff[4], aXor[4];
#pragma unroll
    for (int mt = 0; mt < 4; mt++) {
        int r = wm * 64 + mt * 16 + aRow16;
        aRowOff[mt] = r * 64;
        aXor[mt]    = (r >> 1) & 3;
    }
    int  bRowOff[2], bXor[2];
#pragma unroll
    for (int p = 0; p < 2; p++) {
        int r = wn * 32 + p * 16 + ((bG >> 1) << 3) + bL8;
        bRowOff[p] = r * 64;
        bXor[p]    = (r >> 1) & 3;
    }
    const uint32_t smemBase = (uint32_t)__cvta_generic_to_shared(smem);

    float acc[4][4][4];
#pragma unroll
    for (int i = 0; i < 4; i++)
#pragma unroll
        for (int j = 0; j < 4; j++)
#pragma unroll
            for (int q = 0; q < 4; q++) acc[i][j][q] = 0.f;

    auto issue = [&](int c) {
        int k0 = c * 32;
        char* sAh = smem + (c & 1) * 32768;
        char* sAl = sAh + 8192;
        char* sBh = sAh + 16384;
        char* sBl = sAh + 24576;
        cpasync16(sAh + sRow0 * 64 + sSw0 * 16,
                  Ahi + (size_t)(m0 + sRow0) * GK + k0 + sC16 * 8);
        cpasync16(sAh + sRow1 * 64 + sSw1 * 16,
                  Ahi + (size_t)(m0 + sRow1) * GK + k0 + sC16 * 8);
        cpasync16(sAl + sRow0 * 64 + sSw0 * 16,
                  Alo + (size_t)(m0 + sRow0) * GK + k0 + sC16 * 8);
        cpasync16(sAl + sRow1 * 64 + sSw1 * 16,
                  Alo + (size_t)(m0 + sRow1) * GK + k0 + sC16 * 8);
        int nA = n0 + sRow0, nB = n0 + sRow1;
        int cA = nA < N ? nA : N - 1, cB = nB < N ? nB : N - 1;
        int zA = nA < N ? 16 : 0,     zB = nB < N ? 16 : 0;
        cpasync16z(sBh + sRow0 * 64 + sSw0 * 16,
                   Bhi + (size_t)cA * GK + k0 + sC16 * 8, zA);
        cpasync16z(sBh + sRow1 * 64 + sSw1 * 16,
                   Bhi + (size_t)cB * GK + k0 + sC16 * 8, zB);
        cpasync16z(sBl + sRow0 * 64 + sSw0 * 16,
                   Blo + (size_t)cA * GK + k0 + sC16 * 8, zA);
        cpasync16z(sBl + sRow1 * 64 + sSw1 * 16,
                   Blo + (size_t)cB * GK + k0 + sC16 * 8, zB);
        cp_commit();
    };

    issue(0);
    issue(1);

    for (int c = 0; c < NCH; c++) {
        if (c < NCH - 1) asm volatile("cp.async.wait_group 1;");
        else             asm volatile("cp.async.wait_group 0;");
        __syncthreads();

        uint32_t sAh = smemBase + (c & 1) * 32768;
        uint32_t sAl = sAh + 8192;
        uint32_t sBh = sAh + 16384;
        uint32_t sBl = sAh + 24576;

#pragma unroll
        for (int k16 = 0; k16 < 2; k16++) {
            int segA = k16 * 2 + aKhalf;
            int segB = k16 * 2 + (bG & 1);
            uint32_t afh[4][4], afl[4][4], bfh[2][4], bfl[2][4];
#pragma unroll
            for (int mt = 0; mt < 4; mt++) {
                uint32_t off = aRowOff[mt] + ((segA ^ aXor[mt]) << 4);
                ldmx4(afh[mt], sAh + off);
                ldmx4(afl[mt], sAl + off);
            }
#pragma unroll
            for (int p = 0; p < 2; p++) {
                uint32_t off = bRowOff[p] + ((segB ^ bXor[p]) << 4);
                ldmx4(bfh[p], sBh + off);
                ldmx4(bfl[p], sBl + off);
            }
#pragma unroll
            for (int mt = 0; mt < 4; mt++)
#pragma unroll
                for (int nt = 0; nt < 4; nt++)
                    mma16816(acc[mt][nt], afh[mt], &bfh[nt >> 1][(nt & 1) * 2]);
#pragma unroll
            for (int mt = 0; mt < 4; mt++)
#pragma unroll
                for (int nt = 0; nt < 4; nt++)
                    mma16816(acc[mt][nt], afl[mt], &bfh[nt >> 1][(nt & 1) * 2]);
#pragma unroll
            for (int mt = 0; mt < 4; mt++)
#pragma unroll
                for (int nt = 0; nt < 4; nt++)
                    mma16816(acc[mt][nt], afh[mt], &bfl[nt >> 1][(nt & 1) * 2]);
        }
        __syncthreads();
        if (c + 2 < NCH) issue(c + 2);
    }

    const int quad = lane >> 2, tq = lane & 3;
#pragma unroll
    for (int mt = 0; mt < 4; mt++) {
        int m = m0 + wm * 64 + mt * 16 + quad;
#pragma unroll
        for (int nt = 0; nt < 4; nt++) {
            int n = n0 + wn * 32 + nt * 8 + tq * 2;
            if (n < N) {
                float2 bv = *reinterpret_cast<const float2*>(&bias[n]);
                float2 o0, o1;
                o0.x = acc[mt][nt][0] + bv.x;
                o0.y = acc[mt][nt][1] + bv.y;
                o1.x = acc[mt][nt][2] + bv.x;
                o1.y = acc[mt][nt][3] + bv.y;
                *reinterpret_cast<float2*>(&C[(size_t)m * N + n]) = o0;
                *reinterpret_cast<float2*>(&C[(size_t)(m + 8) * N + n]) = o1;
            }
        }
    }
}

#define GEMM_SMEM (2 * 32768)

// ---------------------------------------------------------------------------
// r7 grid barrier (single atomic, 1 poller/block)
// ---------------------------------------------------------------------------
__device__ __forceinline__ void gbar() {
    __syncthreads();
    if (threadIdx.x == 0) {
        volatile unsigned* vgen = &g_bar_gen;
        unsigned gen = *vgen;
        __threadfence();
        unsigned v = atomicAdd(&g_bar_cnt, 1u);
        if (v == (unsigned)(gridDim.x - 1)) {
            g_bar_cnt = 0;
            __threadfence();
            *vgen = gen + 1;
        } else {
            while (*vgen == gen) {
#if __CUDA_ARCH__ >= 700
                __nanosleep(40);
#endif
            }
        }
        __threadfence();
    }
    __syncthreads();
}

// ---------------------------------------------------------------------------
// Tensor-core persistent recurrence. 4 chunks x 32KB staging, all issued
// upfront, incremental waits. SMEM map (bytes):
//   WAh[0,16K) WAl[16K,32K) WBh[32K,40K) WBl[40K,48K)
//   stage[48K,176K) = 4 chunks x 32KB ({hi 4x4K}{lo 4x4K})
//   part[176K,178K)
// ---------------------------------------------------------------------------
#define RSM_WAH  0
#define RSM_WAL  16384
#define RSM_WBH  32768
#define RSM_WBL  40960
#define RSM_STG  49152
#define RSM_PART (RSM_STG + 4 * 32768)
#define RECUR_SMEM (RSM_PART + 2048)

__global__ __launch_bounds__(NTHR, 1)
void k_recur_mma(const __nv_bfloat16* __restrict__ UhTh,
                 const __nv_bfloat16* __restrict__ UhTl,
                 const __nv_bfloat16* __restrict__ UhtTh,
                 const __nv_bfloat16* __restrict__ UhtTl) {
    extern __shared__ __align__(16) char smem[];
    const uint32_t smemBase = (uint32_t)__cvta_generic_to_shared(smem);

    const int tid   = threadIdx.x;
    const int lane  = tid & 31;
    const int wid   = tid >> 5;
    const int bid   = blockIdx.x;
    const int colA0 = bid * 16;
    const int colB0 = bid * 8;

    const int aRow16 = lane & 15;
    const int aKhalf = lane >> 4;
    const int aXor   = (aRow16 >> 1) & 3;
    const int bL8    = lane & 7;
    const int bG     = lane >> 3;
    const int bXor   = (bL8 >> 1) & 3;

    const int sRow = tid >> 2;
    const int sSeg = tid & 3;
    const int sSw  = sSeg ^ ((sRow >> 1) & 3);

    // ---- load weights into SMEM (once) ----
    for (int u = tid; u < 1024; u += NTHR) {
        int sub = u >> 6, n = (u >> 2) & 15, seg = u & 3;
        int rowp = sub * 16 + n;
        int sw   = seg ^ ((rowp >> 1) & 3);
        size_t src = (size_t)(colA0 + n) * GK + sub * 32 + seg * 8;
        *reinterpret_cast<uint4*>(smem + RSM_WAH + rowp * 64 + sw * 16) =
            *reinterpret_cast<const uint4*>(UhTh + src);
        *reinterpret_cast<uint4*>(smem + RSM_WAL + rowp * 64 + sw * 16) =
            *reinterpret_cast<const uint4*>(UhTl + src);
    }
    for (int u = tid; u < 512; u += NTHR) {
        int sub = u >> 5, n = (u >> 2) & 7, seg = u & 3;
        int rowp = sub * 8 + n;
        int sw   = seg ^ ((rowp >> 1) & 3);
        size_t src = (size_t)(colB0 + n) * GK + sub * 32 + seg * 8;
        *reinterpret_cast<uint4*>(smem + RSM_WBH + rowp * 64 + sw * 16) =
            *reinterpret_cast<const uint4*>(UhtTh + src);
        *reinterpret_cast<uint4*>(smem + RSM_WBL + rowp * 64 + sw * 16) =
            *reinterpret_cast<const uint4*>(UhtTl + src);
    }
    __syncthreads();

    // ---- initial h planes from g_hcur ----
    for (int i = tid; i < (BB * HH) / RBLK; i += NTHR) {
        int idx = bid * ((BB * HH) / RBLK) + i;
        float v = g_hcur[idx];
        __nv_bfloat16 hh = __float2bfloat16(v);
        g_hch[idx] = hh;
        g_hcl[idx] = __float2bfloat16(v - __bfloat162float(hh));
    }
    gbar();

    // stage chunk c (128 K values = 4 subs of 32 K): 8 cp.async per thread
    auto stage = [&](const __nv_bfloat16* Ph, const __nv_bfloat16* Pl, int c) {
        char* b = smem + RSM_STG + c * 32768;
#pragma unroll
        for (int sub = 0; sub < 4; sub++) {
            size_t src = (size_t)sRow * HH + c * 128 + sub * 32 + sSeg * 8;
            uint32_t off = sub * 4096 + sRow * 64 + sSw * 16;
            cpasync16(b + off, Ph + src);
            cpasync16(b + 16384 + off, Pl + src);
        }
        cp_commit();
    };

    for (int t = 0; t < TT; t++) {
        // ================= PHASE A =================
        {
            const int mt = wid & 3;
            const int nb = wid >> 2;
            float acc[4] = {0.f, 0.f, 0.f, 0.f};

            stage(g_hch, g_hcl, 0);
            stage(g_hch, g_hcl, 1);
            stage(g_hch, g_hcl, 2);
            stage(g_hch, g_hcl, 3);

            for (int c = 0; c < 4; c++) {
                if (c == 0)      asm volatile("cp.async.wait_group 3;");
                else if (c == 1) asm volatile("cp.async.wait_group 2;");
                else if (c == 2) asm volatile("cp.async.wait_group 1;");
                else             asm volatile("cp.async.wait_group 0;");
                __syncthreads();

                uint32_t stg = smemBase + RSM_STG + c * 32768;
#pragma unroll
                for (int j = 0; j < 4; j++) {
                    int subg = c * 4 + j;
                    uint32_t bh[4], bl[4];
                    uint32_t ba = smemBase + RSM_WAH +
                                  (subg * 16 + nb * 8 + bL8) * 64 +
                                  ((bG ^ bXor) << 4);
                    ldmx4(bh, ba);
                    ldmx4(bl, ba + (RSM_WAL - RSM_WAH));
#pragma unroll
                    for (int k16 = 0; k16 < 2; k16++) {
                        uint32_t afh[4], afl[4];
                        uint32_t aa = stg + j * 4096 +
                                      (mt * 16 + aRow16) * 64 +
                                      (((k16 * 2 + aKhalf) ^ aXor) << 4);
                        ldmx4(afh, aa);
                        ldmx4(afl, aa + 16384);
                        mma16816(acc, afh, &bh[k16 * 2]);
                        mma16816(acc, afl, &bh[k16 * 2]);
                        mma16816(acc, afh, &bl[k16 * 2]);
                    }
                }
            }

            const int q = lane >> 2, c2 = lane & 3;
            int gn = colA0 + nb * 8 + c2 * 2;
#pragma unroll
            for (int i = 0; i < 2; i++) {
                int r = mt * 16 + q + i * 8;
                float2 gx = *reinterpret_cast<const float2*>(
                    &g_gx[((size_t)t * BB + r) * (3 * HH) + gn]);
                float p0 = gx.x + acc[i * 2 + 0];
                float p1 = gx.y + acc[i * 2 + 1];
                float s0 = 1.f / (1.f + expf(-p0));
                float s1 = 1.f / (1.f + expf(-p1));
                if (gn < HH) {
                    float2 h = *reinterpret_cast<const float2*>(&g_hcur[r * HH + gn]);
                    float rh0 = s0 * h.x, rh1 = s1 * h.y;
                    *reinterpret_cast<uint32_t*>(&g_rhh[r * HH + gn]) =
                        pack_hl_hi(rh0, rh1);
                    *reinterpret_cast<uint32_t*>(&g_rhl[r * HH + gn]) =
                        pack_hl_lo(rh0, rh1);
                } else {
                    *reinterpret_cast<float2*>(&g_z[r * HH + gn - HH]) =
                        make_float2(s0, s1);
                }
            }
        }
        gbar();

        // ================= PHASE B =================
        {
            const int mt = wid & 3;
            const int kh = wid >> 2;
            float acc[4] = {0.f, 0.f, 0.f, 0.f};

            stage(g_rhh, g_rhl, 0);
            stage(g_rhh, g_rhl, 1);
            stage(g_rhh, g_rhl, 2);
            stage(g_rhh, g_rhl, 3);

            for (int c = 0; c < 4; c++) {
                if (c == 0)      asm volatile("cp.async.wait_group 3;");
                else if (c == 1) asm volatile("cp.async.wait_group 2;");
                else if (c == 2) asm volatile("cp.async.wait_group 1;");
                else             asm volatile("cp.async.wait_group 0;");
                __syncthreads();

                uint32_t stg = smemBase + RSM_STG + c * 32768;
#pragma unroll
                for (int jj = 0; jj < 2; jj++) {
                    int j = kh * 2 + jj;            // sub within chunk
                    int subg = c * 4 + j;
                    uint32_t bh[4], bl[4];
                    uint32_t ba = smemBase + RSM_WBH +
                                  (subg * 8 + bL8) * 64 + ((bG ^ bXor) << 4);
                    ldmx4(bh, ba);
                    ldmx4(bl, ba + (RSM_WBL - RSM_WBH));
#pragma unroll
                    for (int k16 = 0; k16 < 2; k16++) {
                        uint32_t afh[4], afl[4];
                        uint32_t aa = stg + j * 4096 +
                                      (mt * 16 + aRow16) * 64 +
                                      (((k16 * 2 + aKhalf) ^ aXor) << 4);
                        ldmx4(afh, aa);
                        ldmx4(afl, aa + 16384);
                        mma16816(acc, afh, &bh[k16 * 2]);
                        mma16816(acc, afl, &bh[k16 * 2]);
                        mma16816(acc, afh, &bl[k16 * 2]);
                    }
                }
            }

            float* sPart = reinterpret_cast<float*>(smem + RSM_PART);
            if (kh == 1) {
#pragma unroll
                for (int i = 0; i < 4; i++)
                    sPart[(mt * 32 + lane) * 4 + i] = acc[i];
            }
            __syncthreads();

            if (kh == 0) {
#pragma unroll
                for (int i = 0; i < 4; i++)
                    acc[i] += sPart[(mt * 32 + lane) * 4 + i];

                const int q = lane >> 2, c2 = lane & 3;
                int gn = colB0 + c2 * 2;
#pragma unroll
                for (int i = 0; i < 2; i++) {
                    int r = mt * 16 + q + i * 8;
                    float2 gx = *reinterpret_cast<const float2*>(
                        &g_gx[((size_t)t * BB + r) * (3 * HH) + 2 * HH + gn]);
                    float ht0 = tanhf(gx.x + acc[i * 2 + 0]);
                    float ht1 = tanhf(gx.y + acc[i * 2 + 1]);
                    float2 zz = *reinterpret_cast<const float2*>(&g_z[r * HH + gn]);
                    float2 hp = *reinterpret_cast<const float2*>(&g_hcur[r * HH + gn]);
                    float hn0 = (1.f - zz.x) * hp.x + zz.x * ht0;
                    float hn1 = (1.f - zz.y) * hp.y + zz.y * ht1;
                    *reinterpret_cast<float2*>(&g_hcur[r * HH + gn]) =
                        make_float2(hn0, hn1);
                    uint32_t ph = pack_hl_hi(hn0, hn1);
                    uint32_t pl = pack_hl_lo(hn0, hn1);
                    *reinterpret_cast<uint32_t*>(&g_hch[r * HH + gn]) = ph;
                    *reinterpret_cast<uint32_t*>(&g_hcl[r * HH + gn]) = pl;
                    size_t o = ((size_t)t * BB + r) * HH + gn;
                    *reinterpret_cast<uint32_t*>(&g_hallh[o]) = ph;
                    *reinterpret_cast<uint32_t*>(&g_halll[o]) = pl;
                }
            }
        }
        gbar();
    }
}

// ---------------------------------------------------------------------------
extern "C" void kernel_launch(void* const* d_in, const int* in_sizes, int n_in,
                              void* d_out, int out_size) {
    const int*   inputs    = (const int*)  d_in[0];
    const float* hidden    = (const float*)d_in[1];
    const float* emb_table = (const float*)d_in[2];
    const float* W_x       = (const float*)d_in[3];
    const float* U_h       = (const float*)d_in[4];
    const float* U_ht      = (const float*)d_in[5];
    const float* b_rzh     = (const float*)d_in[6];
    const float* fc_W      = (const float*)d_in[7];
    const float* fc_b      = (const float*)d_in[8];
    const float* dec_W     = (const float*)d_in[9];
    const float* dec_b     = (const float*)d_in[10];
    float* out = (float*)d_out;

    float *p_emb, *p_gx, *p_inp, *p_hcur, *p_wxT, *p_uT;
    cudaGetSymbolAddress((void**)&p_emb,  g_emb);
    cudaGetSymbolAddress((void**)&p_gx,   g_gx);
    cudaGetSymbolAddress((void**)&p_inp,  g_inp);
    cudaGetSymbolAddress((void**)&p_hcur, g_hcur);
    cudaGetSymbolAddress((void**)&p_wxT,  g_wxT);
    cudaGetSymbolAddress((void**)&p_uT,   g_uT);

    __nv_bfloat16 *p_ahi, *p_alo, *p_hallh, *p_halll;
    __nv_bfloat16 *p_wxh, *p_wxl, *p_fch, *p_fcl, *p_dech, *p_decl;
    __nv_bfloat16 *p_uhTh, *p_uhTl, *p_uhtTh, *p_uhtTl;
    cudaGetSymbolAddress((void**)&p_ahi,   g_ahi);
    cudaGetSymbolAddress((void**)&p_alo,   g_alo);
    cudaGetSymbolAddress((void**)&p_hallh, g_hallh);
    cudaGetSymbolAddress((void**)&p_halll, g_halll);
    cudaGetSymbolAddress((void**)&p_wxh,   g_wxh);
    cudaGetSymbolAddress((void**)&p_wxl,   g_wxl);
    cudaGetSymbolAddress((void**)&p_fch,   g_fch);
    cudaGetSymbolAddress((void**)&p_fcl,   g_fcl);
    cudaGetSymbolAddress((void**)&p_dech,  g_dech);
    cudaGetSymbolAddress((void**)&p_decl,  g_decl);
    cudaGetSymbolAddress((void**)&p_uhTh,  g_uhTh);
    cudaGetSymbolAddress((void**)&p_uhTl,  g_uhTl);
    cudaGetSymbolAddress((void**)&p_uhtTh, g_uhtTh);
    cudaGetSymbolAddress((void**)&p_uhtTl, g_uhtTl);

    cudaFuncSetAttribute(k_recur_mma, cudaFuncAttributeMaxDynamicSharedMemorySize,
                         RECUR_SMEM);
    cudaFuncSetAttribute(k_gemm_tc, cudaFuncAttributeMaxDynamicSharedMemorySize,
                         GEMM_SMEM);

    // 0) weight prep
    for (int l = 0; l < 2; l++)
        k_transpose<<<dim3(48, 16), dim3(32, 8)>>>(
            W_x + (size_t)l * HH * 3 * HH, p_wxT + (size_t)l * 3 * HH * HH,
            HH, 3 * HH);
    {
        int n4;
        n4 = 2 * 3 * HH * HH / 4;
        k_cvt<<<(n4 + 255) / 256, 256>>>(p_wxT, p_wxh, p_wxl, n4);
        n4 = 2 * HH * HH / 4;
        k_cvt<<<(n4 + 255) / 256, 256>>>(fc_W, p_fch, p_fcl, n4);
        n4 = VV * HH / 4;
        k_cvt<<<(n4 + 255) / 256, 256>>>(dec_W, p_dech, p_decl, n4);
    }
    for (int l = 0; l < 2; l++) {
        k_transpose<<<dim3(32, 16), dim3(32, 8)>>>(
            U_h + (size_t)l * HH * 2 * HH, p_uT, HH, 2 * HH);
        k_cvt<<<(2 * HH * HH / 4 + 255) / 256, 256>>>(
            p_uT, p_uhTh + (size_t)l * 2 * HH * HH,
            p_uhTl + (size_t)l * 2 * HH * HH, 2 * HH * HH / 4);
        k_transpose<<<dim3(16, 16), dim3(32, 8)>>>(
            U_ht + (size_t)l * HH * HH, p_uT, HH, HH);
        k_cvt<<<(HH * HH / 4 + 255) / 256, 256>>>(
            p_uT, p_uhtTh + (size_t)l * HH * HH,
            p_uhtTl + (size_t)l * HH * HH, HH * HH / 4);
    }

    // 1) embeddings + convert
    k_gather<<<MALL, 128>>>(inputs, emb_table);
    k_cvt<<<(MALL * HH / 4 + 255) / 256, 256>>>(p_emb, p_ahi, p_alo, MALL * HH / 4);

    // 2) gates_x for layer 0
    k_gemm_tc<<<dim3((3 * HH) / 128, MALL / 128), 256, GEMM_SMEM>>>(
        p_ahi, p_alo, p_wxh, p_wxl, b_rzh, p_gx, 3 * HH);

    long long need = (long long)TT * BB * VV + 2LL * BB * HH;

    for (int l = 0; l < 2; l++) {
        cudaMemcpyAsync(p_hcur, hidden + (size_t)l * BB * HH,
                        (size_t)BB * HH * sizeof(float), cudaMemcpyDeviceToDevice);

        k_recur_mma<<<RBLK, NTHR, RECUR_SMEM>>>(
            p_uhTh + (size_t)l * 2 * HH * HH, p_uhTl + (size_t)l * 2 * HH * HH,
            p_uhtTh + (size_t)l * HH * HH,    p_uhtTl + (size_t)l * HH * HH);

        if ((long long)out_size >= need)
            cudaMemcpyAsync(out + (size_t)TT * BB * VV + (size_t)l * BB * HH, p_hcur,
                            (size_t)BB * HH * sizeof(float), cudaMemcpyDeviceToDevice);

        // fc: inp = h_all @ fc_W[l]^T + fc_b[l]
        k_gemm_tc<<<dim3(HH / 128, MALL / 128), 256, GEMM_SMEM>>>(
            p_hallh, p_halll,
            p_fch + (size_t)l * HH * HH, p_fcl + (size_t)l * HH * HH,
            fc_b + (size_t)l * HH, p_inp, HH);

        k_cvt<<<(MALL * HH / 4 + 255) / 256, 256>>>(p_inp, p_ahi, p_alo,
                                                    MALL * HH / 4);
        if (l == 0) {
            k_gemm_tc<<<dim3((3 * HH) / 128, MALL / 128), 256, GEMM_SMEM>>>(
                p_ahi, p_alo,
                p_wxh + (size_t)3 * HH * HH, p_wxl + (size_t)3 * HH * HH,
                b_rzh + 3 * HH, p_gx, 3 * HH);
        }
    }

    // decoder
    k_gemm_tc<<<dim3((VV + 127) / 128, MALL / 128), 256, GEMM_SMEM>>>(
        p_ahi, p_alo, p_dech, p_decl, dec_b, out, VV);
}

// round 17
// speedup vs baseline: 1.6055x; 1.6055x over previous
#include <cuda_runtime.h>
#include <cuda_bf16.h>
#include <cuda_fp16.h>
#include <math.h>
#include <stdint.h>

// ---------------------------------------------------------------------------
// GRU LM: T=128, B=64, E=H=512, V=10000, 2 layers.
// Round 17: r15 restored exactly (4044us measured: MMA recurrence with
// depth-4 16KB-chunk staging). ONE change: decoder GEMM switched to
// single-product fp16 (k_gemm_16) -> 3x fewer MMAs on the largest GEMM.
// Decoder is a leaf: no error compounding (predicted rel_err ~3e-4 < 1e-3).
// ---------------------------------------------------------------------------

#define TT   128
#define BB   64
#define HH   512
#define VV   10000
#define MALL (TT * BB)   // 8192
#define GK   512

#define RBLK 64          // recurrence blocks
#define NTHR 256

// fp32 scratch
__device__ float g_emb [MALL * HH];
__device__ float g_gx  [MALL * 3 * HH];
__device__ float g_inp [MALL * HH];
__device__ float g_hcur[BB * HH];
__device__ float g_z   [BB * HH];
__device__ float g_wxT [2 * 3 * HH * HH];
__device__ float g_uT  [2 * HH * HH];      // transpose staging

// bf16 hi/lo planes
__device__ __nv_bfloat16 g_ahi  [MALL * GK];
__device__ __nv_bfloat16 g_alo  [MALL * GK];
__device__ __nv_bfloat16 g_hallh[MALL * GK];
__device__ __nv_bfloat16 g_halll[MALL * GK];
__device__ __nv_bfloat16 g_hch  [BB * HH];
__device__ __nv_bfloat16 g_hcl  [BB * HH];
__device__ __nv_bfloat16 g_rhh  [BB * HH];
__device__ __nv_bfloat16 g_rhl  [BB * HH];
__device__ __nv_bfloat16 g_wxh [2 * 3 * HH * HH];
__device__ __nv_bfloat16 g_wxl [2 * 3 * HH * HH];
__device__ __nv_bfloat16 g_fch [2 * HH * HH];
__device__ __nv_bfloat16 g_fcl [2 * HH * HH];
__device__ __nv_bfloat16 g_uhTh [2 * 2 * HH * HH];
__device__ __nv_bfloat16 g_uhTl [2 * 2 * HH * HH];
__device__ __nv_bfloat16 g_uhtTh[2 * HH * HH];
__device__ __nv_bfloat16 g_uhtTl[2 * HH * HH];

// fp16 planes (decoder path)
__device__ __half g_a16  [MALL * GK];
__device__ __half g_dec16[VV * HH];

// grid barrier state (r7, self-resetting)
__device__ unsigned g_bar_cnt = 0;
__device__ unsigned g_bar_gen = 0;

// ---------------------------------------------------------------------------
__global__ void k_gather(const int* __restrict__ inp, const float* __restrict__ tbl) {
    int i   = blockIdx.x;
    int row = inp[i];
    const float4* src = reinterpret_cast<const float4*>(tbl + (size_t)row * HH);
    float4*       dst = reinterpret_cast<float4*>(g_emb + (size_t)i * HH);
    for (int j = threadIdx.x; j < HH / 4; j += blockDim.x) dst[j] = src[j];
}

__global__ void k_transpose(const float* __restrict__ W, float* __restrict__ WT,
                            int K, int N) {
    __shared__ float tile[32][33];
    int k0 = blockIdx.y * 32, n0 = blockIdx.x * 32;
    int tx = threadIdx.x, ty = threadIdx.y;
#pragma unroll
    for (int i = 0; i < 32; i += 8)
        if (k0 + ty + i < K && n0 + tx < N)
            tile[ty + i][tx] = W[(size_t)(k0 + ty + i) * N + n0 + tx];
    __syncthreads();
#pragma unroll
    for (int i = 0; i < 32; i += 8)
        if (n0 + ty + i < N && k0 + tx < K)
            WT[(size_t)(n0 + ty + i) * K + k0 + tx] = tile[tx][ty + i];
}

__global__ void k_cvt(const float* __restrict__ src,
                      __nv_bfloat16* __restrict__ hi,
                      __nv_bfloat16* __restrict__ lo, int n4) {
    int i = blockIdx.x * blockDim.x + threadIdx.x;
    if (i >= n4) return;
    float4 v = reinterpret_cast<const float4*>(src)[i];
    __nv_bfloat16 h0 = __float2bfloat16(v.x), h1 = __float2bfloat16(v.y),
                  h2 = __float2bfloat16(v.z), h3 = __float2bfloat16(v.w);
    __nv_bfloat16 l0 = __float2bfloat16(v.x - __bfloat162float(h0));
    __nv_bfloat16 l1 = __float2bfloat16(v.y - __bfloat162float(h1));
    __nv_bfloat16 l2 = __float2bfloat16(v.z - __bfloat162float(h2));
    __nv_bfloat16 l3 = __float2bfloat16(v.w - __bfloat162float(h3));
    uint2 hv, lv;
    hv.x = (uint32_t)__bfloat16_as_ushort(h0) | ((uint32_t)__bfloat16_as_ushort(h1) << 16);
    hv.y = (uint32_t)__bfloat16_as_ushort(h2) | ((uint32_t)__bfloat16_as_ushort(h3) << 16);
    lv.x = (uint32_t)__bfloat16_as_ushort(l0) | ((uint32_t)__bfloat16_as_ushort(l1) << 16);
    lv.y = (uint32_t)__bfloat16_as_ushort(l2) | ((uint32_t)__bfloat16_as_ushort(l3) << 16);
    reinterpret_cast<uint2*>(hi)[i] = hv;
    reinterpret_cast<uint2*>(lo)[i] = lv;
}

// fp32 -> fp16 single plane
__global__ void k_cvt16(const float* __restrict__ src, __half* __restrict__ dst,
                        int n4) {
    int i = blockIdx.x * blockDim.x + threadIdx.x;
    if (i >= n4) return;
    float4 v = reinterpret_cast<const float4*>(src)[i];
    __half2 a = __floats2half2_rn(v.x, v.y);
    __half2 b = __floats2half2_rn(v.z, v.w);
    uint2 o;
    o.x = *reinterpret_cast<uint32_t*>(&a);
    o.y = *reinterpret_cast<uint32_t*>(&b);
    reinterpret_cast<uint2*>(dst)[i] = o;
}

// ---------------------------------------------------------------------------
// mma.sync helpers
// ---------------------------------------------------------------------------
__device__ __forceinline__ void cpasync16(void* dst_smem, const void* src) {
    uint32_t d = (uint32_t)__cvta_generic_to_shared(dst_smem);
    asm volatile("cp.async.cg.shared.global [%0], [%1], 16;" :: "r"(d), "l"(src));
}
__device__ __forceinline__ void cpasync16z(void* dst_smem, const void* src, int sz) {
    uint32_t d = (uint32_t)__cvta_generic_to_shared(dst_smem);
    asm volatile("cp.async.cg.shared.global [%0], [%1], 16, %2;"
                 :: "r"(d), "l"(src), "r"(sz));
}
__device__ __forceinline__ void cp_commit() { asm volatile("cp.async.commit_group;"); }

__device__ __forceinline__ void ldmx4(uint32_t* r, uint32_t addr) {
    asm volatile("ldmatrix.sync.aligned.m8n8.x4.shared.b16 {%0,%1,%2,%3}, [%4];"
                 : "=r"(r[0]), "=r"(r[1]), "=r"(r[2]), "=r"(r[3]) : "r"(addr));
}
__device__ __forceinline__ void mma16816(float* d, const uint32_t* a, const uint32_t* b) {
    asm volatile(
        "mma.sync.aligned.m16n8k16.row.col.f32.bf16.bf16.f32 "
        "{%0,%1,%2,%3}, {%4,%5,%6,%7}, {%8,%9}, {%0,%1,%2,%3};"
        : "+f"(d[0]), "+f"(d[1]), "+f"(d[2]), "+f"(d[3])
        : "r"(a[0]), "r"(a[1]), "r"(a[2]), "r"(a[3]), "r"(b[0]), "r"(b[1]));
}
__device__ __forceinline__ void mma16816h(float* d, const uint32_t* a, const uint32_t* b) {
    asm volatile(
        "mma.sync.aligned.m16n8k16.row.col.f32.f16.f16.f32 "
        "{%0,%1,%2,%3}, {%4,%5,%6,%7}, {%8,%9}, {%0,%1,%2,%3};"
        : "+f"(d[0]), "+f"(d[1]), "+f"(d[2]), "+f"(d[3])
        : "r"(a[0]), "r"(a[1]), "r"(a[2]), "r"(a[3]), "r"(b[0]), "r"(b[1]));
}

__device__ __forceinline__ uint32_t pack_hl_hi(float x, float y) {
    __nv_bfloat16 hx = __float2bfloat16(x), hy = __float2bfloat16(y);
    return (uint32_t)__bfloat16_as_ushort(hx) | ((uint32_t)__bfloat16_as_ushort(hy) << 16);
}
__device__ __forceinline__ uint32_t pack_hl_lo(float x, float y) {
    __nv_bfloat16 hx = __float2bfloat16(x), hy = __float2bfloat16(y);
    __nv_bfloat16 lx = __float2bfloat16(x - __bfloat162float(hx));
    __nv_bfloat16 ly = __float2bfloat16(y - __bfloat162float(hy));
    return (uint32_t)__bfloat16_as_ushort(lx) | ((uint32_t)__bfloat16_as_ushort(ly) << 16);
}

// ---------------------------------------------------------------------------
// Tensor-core GEMM (r12, measured): interleaved 3-product bf16x3.
// ---------------------------------------------------------------------------
#define NCH 16

__global__ __launch_bounds__(256)
void k_gemm_tc(const __nv_bfloat16* __restrict__ Ahi,
               const __nv_bfloat16* __restrict__ Alo,
               const __nv_bfloat16* __restrict__ Bhi,
               const __nv_bfloat16* __restrict__ Blo,
               const float* __restrict__ bias, float* __restrict__ C, int N) {
    extern __shared__ __align__(16) char smem[];

    const int tid  = threadIdx.x;
    const int lane = tid & 31;
    const int wid  = tid >> 5;
    const int wm   = wid >> 2;
    const int wn   = wid & 3;
    const int m0   = blockIdx.y * 128;
    const int n0   = blockIdx.x * 128;

    const int sRow0 = tid >> 2;
    const int sC16  = tid & 3;
    const int sSw0  = sC16 ^ ((sRow0 >> 1) & 3);
    const int sRow1 = sRow0 + 64;
    const int sSw1  = sC16 ^ ((sRow1 >> 1) & 3);

    const int aRow16 = lane & 15;
    const int aKhalf = lane >> 4;
    const int bL8 = lane & 7, bG = lane >> 3;

    int  aRowOff[4], aXor[4];
#pragma unroll
    for (int mt = 0; mt < 4; mt++) {
        int r = wm * 64 + mt * 16 + aRow16;
        aRowOff[mt] = r * 64;
        aXor[mt]    = (r >> 1) & 3;
    }
    int  bRowOff[2], bXor[2];
#pragma unroll
    for (int p = 0; p < 2; p++) {
        int r = wn * 32 + p * 16 + ((bG >> 1) << 3) + bL8;
        bRowOff[p] = r * 64;
        bXor[p]    = (r >> 1) & 3;
    }
    const uint32_t smemBase = (uint32_t)__cvta_generic_to_shared(smem);

    float acc[4][4][4];
#pragma unroll
    for (int i = 0; i < 4; i++)
#pragma unroll
        for (int j = 0; j < 4; j++)
#pragma unroll
            for (int q = 0; q < 4; q++) acc[i][j][q] = 0.f;

    auto issue = [&](int c) {
        int k0 = c * 32;
        char* sAh = smem + (c & 1) * 32768;
        char* sAl = sAh + 8192;
        char* sBh = sAh + 16384;
        char* sBl = sAh + 24576;
        cpasync16(sAh + sRow0 * 64 + sSw0 * 16,
                  Ahi + (size_t)(m0 + sRow0) * GK + k0 + sC16 * 8);
        cpasync16(sAh + sRow1 * 64 + sSw1 * 16,
                  Ahi + (size_t)(m0 + sRow1) * GK + k0 + sC16 * 8);
        cpasync16(sAl + sRow0 * 64 + sSw0 * 16,
                  Alo + (size_t)(m0 + sRow0) * GK + k0 + sC16 * 8);
        cpasync16(sAl + sRow1 * 64 + sSw1 * 16,
                  Alo + (size_t)(m0 + sRow1) * GK + k0 + sC16 * 8);
        int nA = n0 + sRow0, nB = n0 + sRow1;
        int cA = nA < N ? nA : N - 1, cB = nB < N ? nB : N - 1;
        int zA = nA < N ? 16 : 0,     zB = nB < N ? 16 : 0;
        cpasync16z(sBh + sRow0 * 64 + sSw0 * 16,
                   Bhi + (size_t)cA * GK + k0 + sC16 * 8, zA);
        cpasync16z(sBh + sRow1 * 64 + sSw1 * 16,
                   Bhi + (size_t)cB * GK + k0 + sC16 * 8, zB);
        cpasync16z(sBl + sRow0 * 64 + sSw0 * 16,
                   Blo + (size_t)cA * GK + k0 + sC16 * 8, zA);
        cpasync16z(sBl + sRow1 * 64 + sSw1 * 16,
                   Blo + (size_t)cB * GK + k0 + sC16 * 8, zB);
        cp_commit();
    };

    issue(0);
    issue(1);

    for (int c = 0; c < NCH; c++) {
        if (c < NCH - 1) asm volatile("cp.async.wait_group 1;");
        else             asm volatile("cp.async.wait_group 0;");
        __syncthreads();

        uint32_t sAh = smemBase + (c & 1) * 32768;
        uint32_t sAl = sAh + 8192;
        uint32_t sBh = sAh + 16384;
        uint32_t sBl = sAh + 24576;

#pragma unroll
        for (int k16 = 0; k16 < 2; k16++) {
            int segA = k16 * 2 + aKhalf;
            int segB = k16 * 2 + (bG & 1);
            uint32_t afh[4][4], afl[4][4], bfh[2][4], bfl[2][4];
#pragma unroll
            for (int mt = 0; mt < 4; mt++) {
                uint32_t off = aRowOff[mt] + ((segA ^ aXor[mt]) << 4);
                ldmx4(afh[mt], sAh + off);
                ldmx4(afl[mt], sAl + off);
            }
#pragma unroll
            for (int p = 0; p < 2; p++) {
                uint32_t off = bRowOff[p] + ((segB ^ bXor[p]) << 4);
                ldmx4(bfh[p], sBh + off);
                ldmx4(bfl[p], sBl + off);
            }
#pragma unroll
            for (int mt = 0; mt < 4; mt++)
#pragma unroll
                for (int nt = 0; nt < 4; nt++)
                    mma16816(acc[mt][nt], afh[mt], &bfh[nt >> 1][(nt & 1) * 2]);
#pragma unroll
            for (int mt = 0; mt < 4; mt++)
#pragma unroll
                for (int nt = 0; nt < 4; nt++)
                    mma16816(acc[mt][nt], afl[mt], &bfh[nt >> 1][(nt & 1) * 2]);
#pragma unroll
            for (int mt = 0; mt < 4; mt++)
#pragma unroll
                for (int nt = 0; nt < 4; nt++)
                    mma16816(acc[mt][nt], afh[mt], &bfl[nt >> 1][(nt & 1) * 2]);
        }
        __syncthreads();
        if (c + 2 < NCH) issue(c + 2);
    }

    const int quad = lane >> 2, tq = lane & 3;
#pragma unroll
    for (int mt = 0; mt < 4; mt++) {
        int m = m0 + wm * 64 + mt * 16 + quad;
#pragma unroll
        for (int nt = 0; nt < 4; nt++) {
            int n = n0 + wn * 32 + nt * 8 + tq * 2;
            if (n < N) {
                float2 bv = *reinterpret_cast<const float2*>(&bias[n]);
                float2 o0, o1;
                o0.x = acc[mt][nt][0] + bv.x;
                o0.y = acc[mt][nt][1] + bv.y;
                o1.x = acc[mt][nt][2] + bv.x;
                o1.y = acc[mt][nt][3] + bv.y;
                *reinterpret_cast<float2*>(&C[(size_t)m * N + n]) = o0;
                *reinterpret_cast<float2*>(&C[(size_t)(m + 8) * N + n]) = o1;
            }
        }
    }
}

#define GEMM_SMEM (2 * 32768)

// ---------------------------------------------------------------------------
// fp16 single-product GEMM (decoder): C[M,N] = A[M,512] @ B[N,512]^T + bias.
// 2-stage pipeline, 16KB/stage (A 8KB + B 8KB), one mma group per k16.
// ---------------------------------------------------------------------------
__global__ __launch_bounds__(256)
void k_gemm_16(const __half* __restrict__ A, const __half* __restrict__ B,
               const float* __restrict__ bias, float* __restrict__ C, int N) {
    __shared__ __align__(16) char smem[2 * 16384];

    const int tid  = threadIdx.x;
    const int lane = tid & 31;
    const int wid  = tid >> 5;
    const int wm   = wid >> 2;
    const int wn   = wid & 3;
    const int m0   = blockIdx.y * 128;
    const int n0   = blockIdx.x * 128;

    const int sRow0 = tid >> 2;
    const int sC16  = tid & 3;
    const int sSw0  = sC16 ^ ((sRow0 >> 1) & 3);
    const int sRow1 = sRow0 + 64;
    const int sSw1  = sC16 ^ ((sRow1 >> 1) & 3);

    const int aRow16 = lane & 15;
    const int aKhalf = lane >> 4;
    const int bL8 = lane & 7, bG = lane >> 3;

    int  aRowOff[4], aXor[4];
#pragma unroll
    for (int mt = 0; mt < 4; mt++) {
        int r = wm * 64 + mt * 16 + aRow16;
        aRowOff[mt] = r * 64;
        aXor[mt]    = (r >> 1) & 3;
    }
    int  bRowOff[2], bXor[2];
#pragma unroll
    for (int p = 0; p < 2; p++) {
        int r = wn * 32 + p * 16 + ((bG >> 1) << 3) + bL8;
        bRowOff[p] = r * 64;
        bXor[p]    = (r >> 1) & 3;
    }
    const uint32_t smemBase = (uint32_t)__cvta_generic_to_shared(smem);

    float acc[4][4][4];
#pragma unroll
    for (int i = 0; i < 4; i++)
#pragma unroll
        for (int j = 0; j < 4; j++)
#pragma unroll
            for (int q = 0; q < 4; q++) acc[i][j][q] = 0.f;

    auto issue = [&](int c) {
        int k0 = c * 32;
        char* sA = smem + (c & 1) * 16384;
        char* sB = sA + 8192;
        cpasync16(sA + sRow0 * 64 + sSw0 * 16,
                  A + (size_t)(m0 + sRow0) * GK + k0 + sC16 * 8);
        cpasync16(sA + sRow1 * 64 + sSw1 * 16,
                  A + (size_t)(m0 + sRow1) * GK + k0 + sC16 * 8);
        int nA = n0 + sRow0, nB = n0 + sRow1;
        int cA = nA < N ? nA : N - 1, cB = nB < N ? nB : N - 1;
        cpasync16z(sB + sRow0 * 64 + sSw0 * 16,
                   B + (size_t)cA * GK + k0 + sC16 * 8, nA < N ? 16 : 0);
        cpasync16z(sB + sRow1 * 64 + sSw1 * 16,
                   B + (size_t)cB * GK + k0 + sC16 * 8, nB < N ? 16 : 0);
        cp_commit();
    };

    issue(0);
    issue(1);

    for (int c = 0; c < NCH; c++) {
        if (c < NCH - 1) asm volatile("cp.async.wait_group 1;");
        else             asm volatile("cp.async.wait_group 0;");
        __syncthreads();

        uint32_t sA = smemBase + (c & 1) * 16384;
        uint32_t sB = sA + 8192;

#pragma unroll
        for (int k16 = 0; k16 < 2; k16++) {
            int segA = k16 * 2 + aKhalf;
            int segB = k16 * 2 + (bG & 1);
            uint32_t af[4][4], bf[2][4];
#pragma unroll
            for (int mt = 0; mt < 4; mt++)
                ldmx4(af[mt], sA + aRowOff[mt] + ((segA ^ aXor[mt]) << 4));
#pragma unroll
            for (int p = 0; p < 2; p++)
                ldmx4(bf[p], sB + bRowOff[p] + ((segB ^ bXor[p]) << 4));
#pragma unroll
            for (int mt = 0; mt < 4; mt++)
#pragma unroll
                for (int nt = 0; nt < 4; nt++)
                    mma16816h(acc[mt][nt], af[mt], &bf[nt >> 1][(nt & 1) * 2]);
        }
        __syncthreads();
        if (c + 2 < NCH) issue(c + 2);
    }

    const int quad = lane >> 2, tq = lane & 3;
#pragma unroll
    for (int mt = 0; mt < 4; mt++) {
        int m = m0 + wm * 64 + mt * 16 + quad;
#pragma unroll
        for (int nt = 0; nt < 4; nt++) {
            int n = n0 + wn * 32 + nt * 8 + tq * 2;
            if (n < N) {
                float2 bv = *reinterpret_cast<const float2*>(&bias[n]);
                float2 o0, o1;
                o0.x = acc[mt][nt][0] + bv.x;
                o0.y = acc[mt][nt][1] + bv.y;
                o1.x = acc[mt][nt][2] + bv.x;
                o1.y = acc[mt][nt][3] + bv.y;
                *reinterpret_cast<float2*>(&C[(size_t)m * N + n]) = o0;
                *reinterpret_cast<float2*>(&C[(size_t)(m + 8) * N + n]) = o1;
            }
        }
    }
}

// ---------------------------------------------------------------------------
// r7 grid barrier (single atomic, 1 poller/block)
// ---------------------------------------------------------------------------
__device__ __forceinline__ void gbar() {
    __syncthreads();
    if (threadIdx.x == 0) {
        volatile unsigned* vgen = &g_bar_gen;
        unsigned gen = *vgen;
        __threadfence();
        unsigned v = atomicAdd(&g_bar_cnt, 1u);
        if (v == (unsigned)(gridDim.x - 1)) {
            g_bar_cnt = 0;
            __threadfence();
            *vgen = gen + 1;
        } else {
            while (*vgen == gen) {
#if __CUDA_ARCH__ >= 700
                __nanosleep(40);
#endif
            }
        }
        __threadfence();
    }
    __syncthreads();
}

// ---------------------------------------------------------------------------
// Tensor-core persistent recurrence (r15 EXACT: depth-4, 16KB chunks).
// SMEM map (bytes): WAh[0,16K) WAl[16K,32K) WBh[32K,40K) WBl[40K,48K)
//   stage[48K,112K) = 4 stages x 16KB ({hi 2x4K}{lo 2x4K})
//   part[112K,114K)
// ---------------------------------------------------------------------------
#define RSM_WAH  0
#define RSM_WAL  16384
#define RSM_WBH  32768
#define RSM_WBL  40960
#define RSM_STG  49152
#define RSM_PART (RSM_STG + 4 * 16384)
#define RECUR_SMEM (RSM_PART + 2048)

__global__ __launch_bounds__(NTHR, 1)
void k_recur_mma(const __nv_bfloat16* __restrict__ UhTh,
                 const __nv_bfloat16* __restrict__ UhTl,
                 const __nv_bfloat16* __restrict__ UhtTh,
                 const __nv_bfloat16* __restrict__ UhtTl) {
    extern __shared__ __align__(16) char smem[];
    const uint32_t smemBase = (uint32_t)__cvta_generic_to_shared(smem);

    const int tid   = threadIdx.x;
    const int lane  = tid & 31;
    const int wid   = tid >> 5;
    const int bid   = blockIdx.x;
    const int colA0 = bid * 16;
    const int colB0 = bid * 8;

    const int aRow16 = lane & 15;
    const int aKhalf = lane >> 4;
    const int aXor   = (aRow16 >> 1) & 3;
    const int bL8    = lane & 7;
    const int bG     = lane >> 3;
    const int bXor   = (bL8 >> 1) & 3;

    const int sRow = tid >> 2;
    const int sSeg = tid & 3;
    const int sSw  = sSeg ^ ((sRow >> 1) & 3);

    // ---- load weights into SMEM (once) ----
    for (int u = tid; u < 1024; u += NTHR) {
        int sub = u >> 6, n = (u >> 2) & 15, seg = u & 3;
        int rowp = sub * 16 + n;
        int sw   = seg ^ ((rowp >> 1) & 3);
        size_t src = (size_t)(colA0 + n) * GK + sub * 32 + seg * 8;
        *reinterpret_cast<uint4*>(smem + RSM_WAH + rowp * 64 + sw * 16) =
            *reinterpret_cast<const uint4*>(UhTh + src);
        *reinterpret_cast<uint4*>(smem + RSM_WAL + rowp * 64 + sw * 16) =
            *reinterpret_cast<const uint4*>(UhTl + src);
    }
    for (int u = tid; u < 512; u += NTHR) {
        int sub = u >> 5, n = (u >> 2) & 7, seg = u & 3;
        int rowp = sub * 8 + n;
        int sw   = seg ^ ((rowp >> 1) & 3);
        size_t src = (size_t)(colB0 + n) * GK + sub * 32 + seg * 8;
        *reinterpret_cast<uint4*>(smem + RSM_WBH + rowp * 64 + sw * 16) =
            *reinterpret_cast<const uint4*>(UhtTh + src);
        *reinterpret_cast<uint4*>(smem + RSM_WBL + rowp * 64 + sw * 16) =
            *reinterpret_cast<const uint4*>(UhtTl + src);
    }
    __syncthreads();

    // ---- initial h planes from g_hcur ----
    for (int i = tid; i < (BB * HH) / RBLK; i += NTHR) {
        int idx = bid * ((BB * HH) / RBLK) + i;
        float v = g_hcur[idx];
        __nv_bfloat16 hh = __float2bfloat16(v);
        g_hch[idx] = hh;
        g_hcl[idx] = __float2bfloat16(v - __bfloat162float(hh));
    }
    gbar();

    // staging helper: chunk c (64 K) into buffer (c&3)
    auto stage = [&](const __nv_bfloat16* Ph, const __nv_bfloat16* Pl, int c) {
        char* b = smem + RSM_STG + (c & 3) * 16384;
#pragma unroll
        for (int sub = 0; sub < 2; sub++) {
            size_t src = (size_t)sRow * HH + c * 64 + sub * 32 + sSeg * 8;
            cpasync16(b + sub * 4096 + sRow * 64 + sSw * 16, Ph + src);
            cpasync16(b + 8192 + sub * 4096 + sRow * 64 + sSw * 16, Pl + src);
        }
        cp_commit();
    };

    auto waitc = [&](int c) {
        if (c < 5)      asm volatile("cp.async.wait_group 3;");
        else if (c == 5) asm volatile("cp.async.wait_group 2;");
        else if (c == 6) asm volatile("cp.async.wait_group 1;");
        else             asm volatile("cp.async.wait_group 0;");
    };

    for (int t = 0; t < TT; t++) {
        // ================= PHASE A =================
        {
            const int mt = wid & 3;
            const int nb = wid >> 2;
            float acc[4] = {0.f, 0.f, 0.f, 0.f};

            stage(g_hch, g_hcl, 0);
            stage(g_hch, g_hcl, 1);
            stage(g_hch, g_hcl, 2);
            stage(g_hch, g_hcl, 3);

            for (int c = 0; c < 8; c++) {
                waitc(c);
                __syncthreads();

                uint32_t stg = smemBase + RSM_STG + (c & 3) * 16384;
#pragma unroll
                for (int sub = 0; sub < 2; sub++) {
                    int subg = c * 2 + sub;
                    uint32_t bh[4], bl[4];
                    uint32_t ba = smemBase + RSM_WAH +
                                  (subg * 16 + nb * 8 + bL8) * 64 +
                                  ((bG ^ bXor) << 4);
                    ldmx4(bh, ba);
                    ldmx4(bl, ba + (RSM_WAL - RSM_WAH));
#pragma unroll
                    for (int k16 = 0; k16 < 2; k16++) {
                        uint32_t afh[4], afl[4];
                        uint32_t aa = stg + sub * 4096 +
                                      (mt * 16 + aRow16) * 64 +
                                      (((k16 * 2 + aKhalf) ^ aXor) << 4);
                        ldmx4(afh, aa);
                        ldmx4(afl, aa + 8192);
                        mma16816(acc, afh, &bh[k16 * 2]);
                        mma16816(acc, afl, &bh[k16 * 2]);
                        mma16816(acc, afh, &bl[k16 * 2]);
                    }
                }
                __syncthreads();
                if (c + 4 < 8) stage(g_hch, g_hcl, c + 4);
            }

            const int q = lane >> 2, c2 = lane & 3;
            int gn = colA0 + nb * 8 + c2 * 2;
#pragma unroll
            for (int i = 0; i < 2; i++) {
                int r = mt * 16 + q + i * 8;
                float2 gx = *reinterpret_cast<const float2*>(
                    &g_gx[((size_t)t * BB + r) * (3 * HH) + gn]);
                float p0 = gx.x + acc[i * 2 + 0];
                float p1 = gx.y + acc[i * 2 + 1];
                float s0 = 1.f / (1.f + expf(-p0));
                float s1 = 1.f / (1.f + expf(-p1));
                if (gn < HH) {
                    float2 h = *reinterpret_cast<const float2*>(&g_hcur[r * HH + gn]);
                    float rh0 = s0 * h.x, rh1 = s1 * h.y;
                    *reinterpret_cast<uint32_t*>(&g_rhh[r * HH + gn]) =
                        pack_hl_hi(rh0, rh1);
                    *reinterpret_cast<uint32_t*>(&g_rhl[r * HH + gn]) =
                        pack_hl_lo(rh0, rh1);
                } else {
                    *reinterpret_cast<float2*>(&g_z[r * HH + gn - HH]) =
                        make_float2(s0, s1);
                }
            }
        }
        gbar();

        // ================= PHASE B =================
        {
            const int mt = wid & 3;
            const int kh = wid >> 2;
            float acc[4] = {0.f, 0.f, 0.f, 0.f};

            stage(g_rhh, g_rhl, 0);
            stage(g_rhh, g_rhl, 1);
            stage(g_rhh, g_rhl, 2);
            stage(g_rhh, g_rhl, 3);

            for (int c = 0; c < 8; c++) {
                waitc(c);
                __syncthreads();

                uint32_t stg = smemBase + RSM_STG + (c & 3) * 16384;
                int subg = c * 2 + kh;
                uint32_t bh[4], bl[4];
                uint32_t ba = smemBase + RSM_WBH +
                              (subg * 8 + bL8) * 64 + ((bG ^ bXor) << 4);
                ldmx4(bh, ba);
                ldmx4(bl, ba + (RSM_WBL - RSM_WBH));
#pragma unroll
                for (int k16 = 0; k16 < 2; k16++) {
                    uint32_t afh[4], afl[4];
                    uint32_t aa = stg + kh * 4096 +
                                  (mt * 16 + aRow16) * 64 +
                                  (((k16 * 2 + aKhalf) ^ aXor) << 4);
                    ldmx4(afh, aa);
                    ldmx4(afl, aa + 8192);
                    mma16816(acc, afh, &bh[k16 * 2]);
                    mma16816(acc, afl, &bh[k16 * 2]);
                    mma16816(acc, afh, &bl[k16 * 2]);
                }
                __syncthreads();
                if (c + 4 < 8) stage(g_rhh, g_rhl, c + 4);
            }

            float* sPart = reinterpret_cast<float*>(smem + RSM_PART);
            if (kh == 1) {
#pragma unroll
                for (int i = 0; i < 4; i++)
                    sPart[(mt * 32 + lane) * 4 + i] = acc[i];
            }
            __syncthreads();

            if (kh == 0) {
#pragma unroll
                for (int i = 0; i < 4; i++)
                    acc[i] += sPart[(mt * 32 + lane) * 4 + i];

                const int q = lane >> 2, c2 = lane & 3;
                int gn = colB0 + c2 * 2;
#pragma unroll
                for (int i = 0; i < 2; i++) {
                    int r = mt * 16 + q + i * 8;
                    float2 gx = *reinterpret_cast<const float2*>(
                        &g_gx[((size_t)t * BB + r) * (3 * HH) + 2 * HH + gn]);
                    float ht0 = tanhf(gx.x + acc[i * 2 + 0]);
                    float ht1 = tanhf(gx.y + acc[i * 2 + 1]);
                    float2 zz = *reinterpret_cast<const float2*>(&g_z[r * HH + gn]);
                    float2 hp = *reinterpret_cast<const float2*>(&g_hcur[r * HH + gn]);
                    float hn0 = (1.f - zz.x) * hp.x + zz.x * ht0;
                    float hn1 = (1.f - zz.y) * hp.y + zz.y * ht1;
                    *reinterpret_cast<float2*>(&g_hcur[r * HH + gn]) =
                        make_float2(hn0, hn1);
                    uint32_t ph = pack_hl_hi(hn0, hn1);
                    uint32_t pl = pack_hl_lo(hn0, hn1);
                    *reinterpret_cast<uint32_t*>(&g_hch[r * HH + gn]) = ph;
                    *reinterpret_cast<uint32_t*>(&g_hcl[r * HH + gn]) = pl;
                    size_t o = ((size_t)t * BB + r) * HH + gn;
                    *reinterpret_cast<uint32_t*>(&g_hallh[o]) = ph;
                    *reinterpret_cast<uint32_t*>(&g_halll[o]) = pl;
                }
            }
        }
        gbar();
    }
}

// ---------------------------------------------------------------------------
extern "C" void kernel_launch(void* const* d_in, const int* in_sizes, int n_in,
                              void* d_out, int out_size) {
    const int*   inputs    = (const int*)  d_in[0];
    const float* hidden    = (const float*)d_in[1];
    const float* emb_table = (const float*)d_in[2];
    const float* W_x       = (const float*)d_in[3];
    const float* U_h       = (const float*)d_in[4];
    const float* U_ht      = (const float*)d_in[5];
    const float* b_rzh     = (const float*)d_in[6];
    const float* fc_W      = (const float*)d_in[7];
    const float* fc_b      = (const float*)d_in[8];
    const float* dec_W     = (const float*)d_in[9];
    const float* dec_b     = (const float*)d_in[10];
    float* out = (float*)d_out;

    float *p_emb, *p_gx, *p_inp, *p_hcur, *p_wxT, *p_uT;
    cudaGetSymbolAddress((void**)&p_emb,  g_emb);
    cudaGetSymbolAddress((void**)&p_gx,   g_gx);
    cudaGetSymbolAddress((void**)&p_inp,  g_inp);
    cudaGetSymbolAddress((void**)&p_hcur, g_hcur);
    cudaGetSymbolAddress((void**)&p_wxT,  g_wxT);
    cudaGetSymbolAddress((void**)&p_uT,   g_uT);

    __nv_bfloat16 *p_ahi, *p_alo, *p_hallh, *p_halll;
    __nv_bfloat16 *p_wxh, *p_wxl, *p_fch, *p_fcl;
    __nv_bfloat16 *p_uhTh, *p_uhTl, *p_uhtTh, *p_uhtTl;
    __half *p_a16, *p_dec16;
    cudaGetSymbolAddress((void**)&p_ahi,   g_ahi);
    cudaGetSymbolAddress((void**)&p_alo,   g_alo);
    cudaGetSymbolAddress((void**)&p_hallh, g_hallh);
    cudaGetSymbolAddress((void**)&p_halll, g_halll);
    cudaGetSymbolAddress((void**)&p_wxh,   g_wxh);
    cudaGetSymbolAddress((void**)&p_wxl,   g_wxl);
    cudaGetSymbolAddress((void**)&p_fch,   g_fch);
    cudaGetSymbolAddress((void**)&p_fcl,   g_fcl);
    cudaGetSymbolAddress((void**)&p_uhTh,  g_uhTh);
    cudaGetSymbolAddress((void**)&p_uhTl,  g_uhTl);
    cudaGetSymbolAddress((void**)&p_uhtTh, g_uhtTh);
    cudaGetSymbolAddress((void**)&p_uhtTl, g_uhtTl);
    cudaGetSymbolAddress((void**)&p_a16,   g_a16);
    cudaGetSymbolAddress((void**)&p_dec16, g_dec16);

    cudaFuncSetAttribute(k_recur_mma, cudaFuncAttributeMaxDynamicSharedMemorySize,
                         RECUR_SMEM);
    cudaFuncSetAttribute(k_gemm_tc, cudaFuncAttributeMaxDynamicSharedMemorySize,
                         GEMM_SMEM);

    // 0) weight prep
    for (int l = 0; l < 2; l++)
        k_transpose<<<dim3(48, 16), dim3(32, 8)>>>(
            W_x + (size_t)l * HH * 3 * HH, p_wxT + (size_t)l * 3 * HH * HH,
            HH, 3 * HH);
    {
        int n4;
        n4 = 2 * 3 * HH * HH / 4;
        k_cvt<<<(n4 + 255) / 256, 256>>>(p_wxT, p_wxh, p_wxl, n4);
        n4 = 2 * HH * HH / 4;
        k_cvt<<<(n4 + 255) / 256, 256>>>(fc_W, p_fch, p_fcl, n4);
        n4 = VV * HH / 4;
        k_cvt16<<<(n4 + 255) / 256, 256>>>(dec_W, p_dec16, n4);
    }
    for (int l = 0; l < 2; l++) {
        k_transpose<<<dim3(32, 16), dim3(32, 8)>>>(
            U_h + (size_t)l * HH * 2 * HH, p_uT, HH, 2 * HH);
        k_cvt<<<(2 * HH * HH / 4 + 255) / 256, 256>>>(
            p_uT, p_uhTh + (size_t)l * 2 * HH * HH,
            p_uhTl + (size_t)l * 2 * HH * HH, 2 * HH * HH / 4);
        k_transpose<<<dim3(16, 16), dim3(32, 8)>>>(
            U_ht + (size_t)l * HH * HH, p_uT, HH, HH);
        k_cvt<<<(HH * HH / 4 + 255) / 256, 256>>>(
            p_uT, p_uhtTh + (size_t)l * HH * HH,
            p_uhtTl + (size_t)l * HH * HH, HH * HH / 4);
    }

    // 1) embeddings + convert
    k_gather<<<MALL, 128>>>(inputs, emb_table);
    k_cvt<<<(MALL * HH / 4 + 255) / 256, 256>>>(p_emb, p_ahi, p_alo, MALL * HH / 4);

    // 2) gates_x for layer 0
    k_gemm_tc<<<dim3((3 * HH) / 128, MALL / 128), 256, GEMM_SMEM>>>(
        p_ahi, p_alo, p_wxh, p_wxl, b_rzh, p_gx, 3 * HH);

    long long need = (long long)TT * BB * VV + 2LL * BB * HH;

    for (int l = 0; l < 2; l++) {
        cudaMemcpyAsync(p_hcur, hidden + (size_t)l * BB * HH,
                        (size_t)BB * HH * sizeof(float), cudaMemcpyDeviceToDevice);

        k_recur_mma<<<RBLK, NTHR, RECUR_SMEM>>>(
            p_uhTh + (size_t)l * 2 * HH * HH, p_uhTl + (size_t)l * 2 * HH * HH,
            p_uhtTh + (size_t)l * HH * HH,    p_uhtTl + (size_t)l * HH * HH);

        if ((long long)out_size >= need)
            cudaMemcpyAsync(out + (size_t)TT * BB * VV + (size_t)l * BB * HH, p_hcur,
                            (size_t)BB * HH * sizeof(float), cudaMemcpyDeviceToDevice);

        // fc: inp = h_all @ fc_W[l]^T + fc_b[l]
        k_gemm_tc<<<dim3(HH / 128, MALL / 128), 256, GEMM_SMEM>>>(
            p_hallh, p_halll,
            p_fch + (size_t)l * HH * HH, p_fcl + (size_t)l * HH * HH,
            fc_b + (size_t)l * HH, p_inp, HH);

        if (l == 0) {
            // bf16 planes feed gates_x for layer 1 (protect accuracy)
            k_cvt<<<(MALL * HH / 4 + 255) / 256, 256>>>(p_inp, p_ahi, p_alo,
                                                        MALL * HH / 4);
            k_gemm_tc<<<dim3((3 * HH) / 128, MALL / 128), 256, GEMM_SMEM>>>(
                p_ahi, p_alo,
                p_wxh + (size_t)3 * HH * HH, p_wxl + (size_t)3 * HH * HH,
                b_rzh + 3 * HH, p_gx, 3 * HH);
        } else {
            // fp16 plane feeds the decoder (leaf GEMM, single product)
            k_cvt16<<<(MALL * HH / 4 + 255) / 256, 256>>>(p_inp, p_a16,
                                                          MALL * HH / 4);
        }
    }

    // decoder: single-product fp16
    k_gemm_16<<<dim3((VV + 127) / 128, MALL / 128), 256>>>(
        p_a16, p_dec16, dec_b, out, VV);
}